// round 5
// baseline (speedup 1.0000x reference)
#include <cuda_runtime.h>
#include <cstdint>

// SKA: out[n, g*8+c, h, w] = sum_{7x7} x_pad[n, g*8+c, h+i, w+j] * w[n, c, i*7+j, h, w]
// x [8,512,96,96] f32, w [8,8,49,96,96] f32, out [8,512,96,96] f32.
//
// R4 design: each thread owns TWO vertically-adjacent f32x2 output pairs
// (rows 2q, 2q+1). Their 7-row x windows share 6 rows -> one 8-row sweep
// feeds both pixels: 64 B of LDS per output float (was 112). 2x49 weight
// pairs live in 196 registers for the whole 64-g loop (192 thr/CTA, ~240 regs).
// x streams via cp.async: 4 buffers x 2 channels, wait_group 2 (>=2 compute
// phases of DRAM-latency slack). Shifted odd-tap packs are built once per
// tile row and shared by both pixels.

#define N_    8
#define IC    512
#define H_    96
#define W_    96
#define WC    8
#define G_    64
#define KS    7
#define PAD   3
#define HT    8
#define PAIRS 48
#define NTHR  192                   // 4 row-groups x 48 pairs
#define TROWS (HT + 2 * PAD)        // 14
#define PITCH 104                   // 3 zero | 96 data | 5 zero (floats)
#define TILE_F (TROWS * PITCH)      // 1456 floats per channel slab
#define HW    (H_ * W_)             // 9216
#define CSTR  ((size_t)WC * HW)     // x/out channel stride between g steps
#define NIT   (G_ / 2)              // 32 pipeline stages

typedef unsigned long long u64;

static __device__ __forceinline__ void ffma2(u64& d, u64 a, u64 b) {
    asm("fma.rn.f32x2 %0, %1, %2, %0;" : "+l"(d) : "l"(a), "l"(b));
}
static __device__ __forceinline__ u64 fadd2(u64 a, u64 b) {
    u64 d; asm("add.rn.f32x2 %0, %1, %2;" : "=l"(d) : "l"(a), "l"(b)); return d;
}
static __device__ __forceinline__ void unpack2(u64 v, float& a, float& b) {
    asm("mov.b64 {%0, %1}, %2;" : "=f"(a), "=f"(b) : "l"(v));
}
static __device__ __forceinline__ u64 pack2(float a, float b) {
    u64 r; asm("mov.b64 %0, {%1, %2};" : "=l"(r) : "f"(a), "f"(b)); return r;
}
static __device__ __forceinline__ void cp4(uint32_t s, const float* g, int sz) {
    asm volatile("cp.async.ca.shared.global [%0], [%1], 4, %2;"
                 :: "r"(s), "l"(g), "r"(sz));
}

__global__ __launch_bounds__(NTHR, 1)
void ska_kernel(const float* __restrict__ x, const float* __restrict__ wgt,
                float* __restrict__ out) {
    __shared__ float smem[8 * TILE_F];   // 4 buffers x 2 channel slabs = 46.6 KB

    const int tid = threadIdx.x;
    const int ht  = blockIdx.x;          // 0..11
    const int c   = blockIdx.y;          // 0..7
    const int n   = blockIdx.z;          // 0..7
    const int h0  = ht * HT;
    const int q   = tid / PAIRS;         // 0..3 -> output rows 2q, 2q+1
    const int p   = tid % PAIRS;
    const int r0  = 2 * q;
    const int w0  = 2 * p;

    // Zero the left/right halo columns of all 8 slabs (written once).
    for (int z = tid; z < 8 * TROWS * 8; z += NTHR) {
        int b = z / (TROWS * 8), rem = z % (TROWS * 8);
        int row = rem / 8, ci = rem % 8;
        int col = (ci < 3) ? ci : 99 + (ci - 3);
        smem[b * TILE_F + row * PITCH + col] = 0.0f;
    }

    // Register-cache both pixels' 49 weight pairs (reused for all 64 g).
    const float* wb = wgt + ((size_t)(n * WC + c) * 49) * HW
                          + (size_t)(h0 + r0) * W_ + w0;
    u64 W0[49], W1[49];
    #pragma unroll
    for (int t = 0; t < 49; t++) {
        W0[t] = *(const u64*)(wb + (size_t)t * HW);
        W1[t] = *(const u64*)(wb + (size_t)t * HW + W_);
    }

    const float* xc = x + (size_t)n * IC * HW + (size_t)c * HW;  // g=0 channel
    const uint32_t sbase = (uint32_t)__cvta_generic_to_shared(smem);

    // Hoisted staging descriptors: exactly 7 elements/thread/slab (7*192=1344).
    uint32_t soff[7];   // smem byte offset within a slab
    int      gofs[7];   // float offset within a channel (row-clamped)
    int      gsz[7];    // 4 = copy, 0 = zero-fill (OOB row)
    #pragma unroll
    for (int k = 0; k < 7; k++) {
        int idx = tid + k * NTHR;            // 0..1343
        int row = idx / W_, col = idx - row * W_;
        int hr  = h0 - PAD + row;
        gsz[k]  = (hr >= 0 && hr < H_) ? 4 : 0;
        int hrc = hr < 0 ? 0 : (hr >= H_ ? H_ - 1 : hr);
        soff[k] = (uint32_t)(row * PITCH + 3 + col) * 4u;
        gofs[k] = hrc * W_ + col;
    }

    // Stage channels (2s, 2s+1) into buffer s%4 and commit one group.
    auto stage = [&](int s) {
        #pragma unroll
        for (int cc = 0; cc < 2; cc++) {
            uint32_t sb = sbase + (uint32_t)(((s & 3) * 2 + cc) * TILE_F) * 4u;
            const float* base = xc + (size_t)(2 * s + cc) * CSTR;
            #pragma unroll
            for (int k = 0; k < 7; k++)
                cp4(sb + soff[k], base + gofs[k], gsz[k]);
        }
        asm volatile("cp.async.commit_group;");
    };

    stage(0);
    stage(1);

    float* op = out + (size_t)n * IC * HW + (size_t)c * HW
                    + (size_t)(h0 + r0) * W_ + w0;

    for (int it = 0; it < NIT; ++it) {
        // Keep 2 stages in flight; ensure group `it` has landed.
        if (it + 2 < NIT) {
            stage(it + 2);
            asm volatile("cp.async.wait_group 2;");
        } else if (it == NIT - 2) {
            asm volatile("cp.async.wait_group 1;");
        } else {
            asm volatile("cp.async.wait_group 0;");
        }
        __syncthreads();
        // Barrier also proves all threads finished compute on buffer (it+2)%4
        // (used at iter it-2) before this iter's staging overwrote it: each
        // thread stages AFTER passing the barrier of iter it-1.

        const float* tbB = smem + (it & 3) * 2 * TILE_F;
        #pragma unroll
        for (int gg = 0; gg < 2; gg++) {
            const float* tb = tbB + gg * TILE_F;
            u64 aE0 = 0ull, aO0 = 0ull;   // pixel0 (row r0): even/odd tap chains
            u64 aE1 = 0ull, aO1 = 0ull;   // pixel1 (row r0+1)
            #pragma unroll
            for (int k = 0; k < 8; k++) { // tile rows r0+k feed both pixels
                const u64* rp = (const u64*)(tb + (r0 + k) * PITCH + w0); // 8B al.
                u64 U0 = rp[0], U1 = rp[1], U2 = rp[2], U3 = rp[3];
                float f0, f1, f2, f3, f4, f5, f6, f7;
                unpack2(U0, f0, f1); unpack2(U1, f2, f3);
                unpack2(U2, f4, f5); unpack2(U3, f6, f7);
                u64 S1 = pack2(f1, f2), S3 = pack2(f3, f4), S5 = pack2(f5, f6);
                if (k < 7) {              // pixel0, kernel row i = k
                    ffma2(aE0, U0, W0[k * 7 + 0]);
                    ffma2(aE0, U1, W0[k * 7 + 2]);
                    ffma2(aE0, U2, W0[k * 7 + 4]);
                    ffma2(aE0, U3, W0[k * 7 + 6]);
                    ffma2(aO0, S1, W0[k * 7 + 1]);
                    ffma2(aO0, S3, W0[k * 7 + 3]);
                    ffma2(aO0, S5, W0[k * 7 + 5]);
                }
                if (k >= 1) {             // pixel1, kernel row i = k-1
                    const int i = k - 1;
                    ffma2(aE1, U0, W1[i * 7 + 0]);
                    ffma2(aE1, U1, W1[i * 7 + 2]);
                    ffma2(aE1, U2, W1[i * 7 + 4]);
                    ffma2(aE1, U3, W1[i * 7 + 6]);
                    ffma2(aO1, S1, W1[i * 7 + 1]);
                    ffma2(aO1, S3, W1[i * 7 + 3]);
                    ffma2(aO1, S5, W1[i * 7 + 5]);
                }
            }
            *(u64*)op        = fadd2(aE0, aO0);
            *(u64*)(op + W_) = fadd2(aE1, aO1);
            op += CSTR;
        }
    }
}

extern "C" void kernel_launch(void* const* d_in, const int* in_sizes, int n_in,
                              void* d_out, int out_size) {
    const float* x = (const float*)d_in[0];
    const float* w = (const float*)d_in[1];
    // x (37,748,736 elems) > w (28,901,376); guard against input ordering.
    if (n_in >= 2 && in_sizes[0] < in_sizes[1]) {
        const float* t = x; x = w; w = t;
    }
    float* out = (float*)d_out;
    dim3 grid(H_ / HT, WC, N_);   // (12, 8, 8) = 768 CTAs
    ska_kernel<<<grid, NTHR>>>(x, w, out);
}

// round 6
// speedup vs baseline: 1.1754x; 1.1754x over previous
#include <cuda_runtime.h>
#include <cstdint>

// SKA: out[n, g*8+c, h, w] = sum_{7x7} x_pad[n, g*8+c, h+i, w+j] * w[n, c, i*7+j, h, w]
// x [8,512,96,96] f32, w [8,8,49,96,96] f32, out [8,512,96,96] f32.
//
// R6: back to the R3 dataflow (1 f32x2 output pair per thread, 49 weight pairs
// register-cached across all 64 g; even taps packed fma.rn.f32x2, odd taps
// scalar FMAs on free pair-splits). Two latency fixes at the structural
// 12-warp/SM cap:
//  - CTA = 4 output rows, 192 threads, __launch_bounds__(192,2): TWO independent
//    CTAs co-resident per SM -> decoupled barriers, one CTA computes while the
//    other syncs/refills.
//  - 4-buffer cp.async pipeline, depth 3 (wait_group 2 BEFORE the barrier, so
//    cross-thread smem visibility is correct; stage it+3 after the barrier).

#define N_    8
#define IC    512
#define H_    96
#define W_    96
#define WC    8
#define G_    64
#define KS    7
#define PAD   3
#define HT    4                     // output rows per CTA
#define PAIRS 48
#define NTHR  (PAIRS * HT)          // 192
#define TROWS (HT + 2 * PAD)        // 10 staged rows
#define PITCH 104                   // 3 zero | 96 data | 5 zero (floats)
#define TILE_F (TROWS * PITCH)      // 1040 floats per channel slab
#define HW    (H_ * W_)             // 9216
#define CSTR  ((size_t)WC * HW)     // x/out channel stride between g steps
#define NIT   (G_ / 2)              // 32 pipeline stages (2 channels each)
#define ELPT  ((TROWS * W_) / NTHR) // 5 staged elements per thread per channel

typedef unsigned long long u64;

static __device__ __forceinline__ void ffma2(u64& d, u64 a, u64 b) {
    asm("fma.rn.f32x2 %0, %1, %2, %0;" : "+l"(d) : "l"(a), "l"(b));
}
// lo += xl*w.lo, hi += xh*w.hi; splitting the weight pair is register aliasing.
static __device__ __forceinline__ void odd_tap(float& lo, float& hi,
                                               float xl, float xh, u64 w) {
    asm("{\n\t"
        ".reg .f32 wl, wh;\n\t"
        "mov.b64 {wl, wh}, %4;\n\t"
        "fma.rn.f32 %0, %2, wl, %0;\n\t"
        "fma.rn.f32 %1, %3, wh, %1;\n\t"
        "}" : "+f"(lo), "+f"(hi) : "f"(xl), "f"(xh), "l"(w));
}
static __device__ __forceinline__ void unpack2(u64 v, float& a, float& b) {
    asm("mov.b64 {%0, %1}, %2;" : "=f"(a), "=f"(b) : "l"(v));
}
static __device__ __forceinline__ u64 pack2(float a, float b) {
    u64 r; asm("mov.b64 %0, {%1, %2};" : "=l"(r) : "f"(a), "f"(b)); return r;
}
static __device__ __forceinline__ void cp4(uint32_t s, const float* g, int sz) {
    asm volatile("cp.async.ca.shared.global [%0], [%1], 4, %2;"
                 :: "r"(s), "l"(g), "r"(sz));
}

__global__ __launch_bounds__(NTHR, 2)
void ska_kernel(const float* __restrict__ x, const float* __restrict__ wgt,
                float* __restrict__ out) {
    __shared__ float smem[8 * TILE_F];   // 4 buffers x 2 channel slabs = 32.5 KB

    const int tid = threadIdx.x;
    const int ht  = blockIdx.x;          // 0..23
    const int c   = blockIdx.y;          // 0..7
    const int n   = blockIdx.z;          // 0..7
    const int h0  = ht * HT;
    const int r   = tid / PAIRS;         // 0..3
    const int p   = tid % PAIRS;
    const int h   = h0 + r;
    const int w0  = 2 * p;

    // Zero left/right halo columns of all 8 slabs (written once, never again).
    for (int z = tid; z < 8 * TROWS * 8; z += NTHR) {
        int b = z / (TROWS * 8), rem = z % (TROWS * 8);
        int row = rem / 8, ci = rem % 8;
        int col = (ci < 3) ? ci : 99 + (ci - 3);
        smem[b * TILE_F + row * PITCH + col] = 0.0f;
    }

    // Register-cache this pixel-pair's 49 weight pairs (reused for all 64 g).
    const float* wb = wgt + ((size_t)(n * WC + c) * 49) * HW + (size_t)h * W_ + w0;
    u64 Wr[49];
    #pragma unroll
    for (int t = 0; t < 49; t++) Wr[t] = *(const u64*)(wb + (size_t)t * HW);

    const float* xc = x + (size_t)n * IC * HW + (size_t)c * HW;  // g=0 channel
    const uint32_t sbase = (uint32_t)__cvta_generic_to_shared(smem);

    // Hoisted staging descriptors: exactly ELPT=5 elements/thread/channel.
    uint32_t soff[ELPT];   // smem byte offset within a slab
    int      gofs[ELPT];   // float offset within a channel (row-clamped)
    int      gsz[ELPT];    // 4 = copy, 0 = zero-fill (OOB row)
    #pragma unroll
    for (int k = 0; k < ELPT; k++) {
        int idx = tid + k * NTHR;            // 0..959
        int row = idx / W_, col = idx - row * W_;
        int hr  = h0 - PAD + row;
        gsz[k]  = (hr >= 0 && hr < H_) ? 4 : 0;
        int hrc = hr < 0 ? 0 : (hr >= H_ ? H_ - 1 : hr);
        soff[k] = (uint32_t)(row * PITCH + 3 + col) * 4u;
        gofs[k] = hrc * W_ + col;
    }

    // Stage channels (2s, 2s+1) into buffer s%4; commit one cp.async group.
    auto stage = [&](int s) {
        #pragma unroll
        for (int cc = 0; cc < 2; cc++) {
            uint32_t sb = sbase + (uint32_t)(((s & 3) * 2 + cc) * TILE_F) * 4u;
            const float* base = xc + (size_t)(2 * s + cc) * CSTR;
            #pragma unroll
            for (int k = 0; k < ELPT; k++)
                cp4(sb + soff[k], base + gofs[k], gsz[k]);
        }
        asm volatile("cp.async.commit_group;");
    };

    stage(0);
    stage(1);
    stage(2);

    float* op = out + (size_t)n * IC * HW + (size_t)c * HW + (size_t)h * W_ + w0;

    for (int it = 0; it < NIT; ++it) {
        // Group `it` must be complete in THIS thread before the barrier makes
        // its smem writes visible to everyone.
        if (it + 1 < NIT) { asm volatile("cp.async.wait_group 2;"); }
        else             { asm volatile("cp.async.wait_group 0;"); }
        __syncthreads();
        // Stage buffer (it+3)%4 = (it-1)%4: legal, the barrier just proved all
        // threads finished compute on it-1.
        if (it + 3 < NIT) stage(it + 3);

        const float* tbB = smem + (it & 3) * 2 * TILE_F;
        #pragma unroll
        for (int gg = 0; gg < 2; gg++) {
            const float* tb = tbB + gg * TILE_F;
            u64 aE0 = 0ull, aE1 = 0ull;       // packed chains (even taps)
            float sLo = 0.0f, sHi = 0.0f;     // scalar chains (odd taps)
            #pragma unroll
            for (int i = 0; i < KS; i++) {
                const u64* rp = (const u64*)(tb + (r + i) * PITCH + w0); // 8B al.
                u64 U0 = rp[0], U1 = rp[1], U2 = rp[2], U3 = rp[3];
                float f0, f1, f2, f3, f4, f5, f6, f7;
                unpack2(U0, f0, f1); unpack2(U1, f2, f3);
                unpack2(U2, f4, f5); unpack2(U3, f6, f7);
                u64& A = (i & 1) ? aE1 : aE0;
                ffma2(A, U0, Wr[i * 7 + 0]);
                ffma2(A, U1, Wr[i * 7 + 2]);
                ffma2(A, U2, Wr[i * 7 + 4]);
                ffma2(A, U3, Wr[i * 7 + 6]);
                odd_tap(sLo, sHi, f1, f2, Wr[i * 7 + 1]);
                odd_tap(sLo, sHi, f3, f4, Wr[i * 7 + 3]);
                odd_tap(sLo, sHi, f5, f6, Wr[i * 7 + 5]);
            }
            float p0, p1, q0, q1;
            unpack2(aE0, p0, p1);
            unpack2(aE1, q0, q1);
            *(u64*)op = pack2(p0 + q0 + sLo, p1 + q1 + sHi);
            op += CSTR;
        }
    }
}

extern "C" void kernel_launch(void* const* d_in, const int* in_sizes, int n_in,
                              void* d_out, int out_size) {
    const float* x = (const float*)d_in[0];
    const float* w = (const float*)d_in[1];
    // x (37,748,736 elems) > w (28,901,376); guard against input ordering.
    if (n_in >= 2 && in_sizes[0] < in_sizes[1]) {
        const float* t = x; x = w; w = t;
    }
    float* out = (float*)d_out;
    dim3 grid(H_ / HT, WC, N_);   // (24, 8, 8) = 1536 CTAs, 2 per SM
    ska_kernel<<<grid, NTHR>>>(x, w, out);
}